// round 1
// baseline (speedup 1.0000x reference)
#include <cuda_runtime.h>
#include <math.h>

#define DIMC    1024
#define NHEADS  16
#define HDIM    64
#define BB      4
#define TTOK    2048
#define NTOK    (BB * TTOK)      // 8192

// ---------------- scratch (device globals; no allocations allowed) ----------
__device__ float g_q[NTOK * DIMC];    // [B,H,T,Dh]
__device__ float g_k[NTOK * DIMC];
__device__ float g_v[NTOK * DIMC];
__device__ float g_att[NTOK * DIMC];  // [B,T,DIM]

// ============================================================================
// GEMM (NT): out[m][n] = sum_c A[m][c] * W[n][c]
// A: [M, DIMC] row-major, W: [DIMC, DIMC] row-major.
// BM=BN=128, BK=8, 256 threads, 8x8 micro-tile per thread.
// qkv_mode=1: write into [B,H,T,Dh] layout. qkv_mode=0: plain row-major.
// ============================================================================
#define BM 128
#define BN 128
#define BK 8

__global__ __launch_bounds__(256)
void gemm_nt_kernel(const float* __restrict__ A, const float* __restrict__ W,
                    float* __restrict__ out, int qkv_mode)
{
    __shared__ __align__(16) float As[BK][BM + 4];   // stride 132 floats = 528B (16B mult)
    __shared__ __align__(16) float Ws[BK][BN + 4];

    const int m0 = blockIdx.x * BM;
    const int n0 = blockIdx.y * BN;
    const int tid = threadIdx.x;
    const int ty = tid >> 4;        // 0..15  (rows)
    const int tx = tid & 15;        // 0..15  (cols)

    float acc[8][8];
#pragma unroll
    for (int i = 0; i < 8; i++)
#pragma unroll
        for (int j = 0; j < 8; j++) acc[i][j] = 0.f;

    // Each thread loads one float4 of A-tile and one of W-tile per k-step.
    const int lr = tid >> 1;          // 0..127: row within tile
    const int lc = (tid & 1) * 4;     // 0 or 4: starting col within 8-wide k slab

    const float* Aptr = A + (size_t)(m0 + lr) * DIMC + lc;
    const float* Wptr = W + (size_t)(n0 + lr) * DIMC + lc;

    for (int k0 = 0; k0 < DIMC; k0 += BK) {
        float4 av = *reinterpret_cast<const float4*>(Aptr + k0);
        float4 wv = *reinterpret_cast<const float4*>(Wptr + k0);
        As[lc + 0][lr] = av.x; As[lc + 1][lr] = av.y;
        As[lc + 2][lr] = av.z; As[lc + 3][lr] = av.w;
        Ws[lc + 0][lr] = wv.x; Ws[lc + 1][lr] = wv.y;
        Ws[lc + 2][lr] = wv.z; Ws[lc + 3][lr] = wv.w;
        __syncthreads();

#pragma unroll
        for (int k = 0; k < BK; k++) {
            float4 a0 = *reinterpret_cast<const float4*>(&As[k][ty * 8]);
            float4 a1 = *reinterpret_cast<const float4*>(&As[k][ty * 8 + 4]);
            float4 b0 = *reinterpret_cast<const float4*>(&Ws[k][tx * 8]);
            float4 b1 = *reinterpret_cast<const float4*>(&Ws[k][tx * 8 + 4]);
            float a[8] = {a0.x, a0.y, a0.z, a0.w, a1.x, a1.y, a1.z, a1.w};
            float b[8] = {b0.x, b0.y, b0.z, b0.w, b1.x, b1.y, b1.z, b1.w};
#pragma unroll
            for (int i = 0; i < 8; i++)
#pragma unroll
                for (int j = 0; j < 8; j++) acc[i][j] = fmaf(a[i], b[j], acc[i][j]);
        }
        __syncthreads();
    }

    if (qkv_mode) {
        // out index: ((b*NHEADS + h)*TTOK + t)*HDIM + d
        const int b  = m0 / TTOK;
        const int t0 = m0 % TTOK;
        const int col0 = n0 + tx * 8;        // 8 cols, never crossing a 64-boundary
        const int h  = col0 / HDIM;
        const int d0 = col0 % HDIM;
#pragma unroll
        for (int i = 0; i < 8; i++) {
            const int t = t0 + ty * 8 + i;
            float* dst = out + ((size_t)(b * NHEADS + h) * TTOK + t) * HDIM + d0;
            float4 r0 = {acc[i][0], acc[i][1], acc[i][2], acc[i][3]};
            float4 r1 = {acc[i][4], acc[i][5], acc[i][6], acc[i][7]};
            *reinterpret_cast<float4*>(dst)     = r0;
            *reinterpret_cast<float4*>(dst + 4) = r1;
        }
    } else {
#pragma unroll
        for (int i = 0; i < 8; i++) {
            float* dst = out + (size_t)(m0 + ty * 8 + i) * DIMC + n0 + tx * 8;
            float4 r0 = {acc[i][0], acc[i][1], acc[i][2], acc[i][3]};
            float4 r1 = {acc[i][4], acc[i][5], acc[i][6], acc[i][7]};
            *reinterpret_cast<float4*>(dst)     = r0;
            *reinterpret_cast<float4*>(dst + 4) = r1;
        }
    }
}

// ============================================================================
// Flash attention, fp32, causal. One block = (64 queries) x (one b*h).
// Q/K/V in [B,H,T,Dh]. Output written to g_att in [B,T,DIM] layout.
// ============================================================================
#define BQ   64
#define BKV  64
#define APAD 4
#define NEG_BIG (-1e30f)

struct AttnSmem {
    float Qs[HDIM][BQ + APAD];    // [d][q], pre-scaled
    float Ks[HDIM][BKV + APAD];   // [d][k]
    float Vs[BKV][HDIM + APAD];   // [k][d]
    float Ss[BQ][BKV + APAD];     // scores then P
    float rowm[BQ];
    float rowl[BQ];
    float alpha[BQ];
};

__global__ __launch_bounds__(256)
void attn_kernel(const float* __restrict__ Q, const float* __restrict__ K,
                 const float* __restrict__ V, float* __restrict__ Out)
{
    extern __shared__ __align__(16) char smem_raw[];
    AttnSmem& s = *reinterpret_cast<AttnSmem*>(smem_raw);

    const int qt  = blockIdx.x;
    const int bh  = blockIdx.y;          // b*NHEADS + h
    const int q0  = qt * BQ;
    const int tid = threadIdx.x;
    const int ty  = tid >> 4;            // 0..15: q row group (4 rows)
    const int tx  = tid & 15;            // 0..15: k/d col group (4 cols)

    const float* Qp = Q + (size_t)bh * TTOK * HDIM;
    const float* Kp = K + (size_t)bh * TTOK * HDIM;
    const float* Vp = V + (size_t)bh * TTOK * HDIM;

    const float scale = 0.125f;          // 1/sqrt(64)

    // Load Q tile transposed + pre-scaled
    for (int idx = tid; idx < BQ * HDIM; idx += 256) {
        const int q = idx >> 6;
        const int d = idx & 63;
        s.Qs[d][q] = Qp[(size_t)(q0 + q) * HDIM + d] * scale;
    }
    if (tid < BQ) { s.rowm[tid] = NEG_BIG; s.rowl[tid] = 0.f; }

    float o[4][4];
#pragma unroll
    for (int i = 0; i < 4; i++)
#pragma unroll
        for (int j = 0; j < 4; j++) o[i][j] = 0.f;

    for (int jt = 0; jt <= qt; jt++) {
        const int k0 = jt * BKV;
        __syncthreads();   // prior-iter PV reads done; Q load visible (first iter)

        for (int idx = tid; idx < BKV * HDIM; idx += 256) {
            const int kk = idx >> 6;
            const int d  = idx & 63;
            s.Ks[d][kk] = Kp[(size_t)(k0 + kk) * HDIM + d];
            s.Vs[kk][d] = Vp[(size_t)(k0 + kk) * HDIM + d];
        }
        __syncthreads();

        // S = (Q*scale) . K^T  -> 4x4 per thread
        float acc[4][4];
#pragma unroll
        for (int i = 0; i < 4; i++)
#pragma unroll
            for (int j = 0; j < 4; j++) acc[i][j] = 0.f;

#pragma unroll 16
        for (int d = 0; d < HDIM; d++) {
            float4 qv = *reinterpret_cast<const float4*>(&s.Qs[d][ty * 4]);
            float4 kv = *reinterpret_cast<const float4*>(&s.Ks[d][tx * 4]);
            float qa[4] = {qv.x, qv.y, qv.z, qv.w};
            float kb[4] = {kv.x, kv.y, kv.z, kv.w};
#pragma unroll
            for (int i = 0; i < 4; i++)
#pragma unroll
                for (int j = 0; j < 4; j++) acc[i][j] = fmaf(qa[i], kb[j], acc[i][j]);
        }

        const bool diag = (jt == qt);
#pragma unroll
        for (int i = 0; i < 4; i++) {
            const int qg = q0 + ty * 4 + i;
            float4 r;
            float* rp = &r.x;
#pragma unroll
            for (int j = 0; j < 4; j++) {
                float v = acc[i][j];
                if (diag && (k0 + tx * 4 + j > qg)) v = NEG_BIG;
                rp[j] = v;
            }
            *reinterpret_cast<float4*>(&s.Ss[ty * 4 + i][tx * 4]) = r;
        }
        __syncthreads();

        // Online softmax, one row per thread (tid < 64)
        if (tid < BQ) {
            const int q = tid;
            const float mo = s.rowm[q];
            float mx = mo;
#pragma unroll 8
            for (int k = 0; k < BKV; k++) mx = fmaxf(mx, s.Ss[q][k]);
            const float al = __expf(mo - mx);
            float l = s.rowl[q] * al;
#pragma unroll 8
            for (int k = 0; k < BKV; k++) {
                const float p = __expf(s.Ss[q][k] - mx);
                s.Ss[q][k] = p;
                l += p;
            }
            s.rowm[q] = mx; s.rowl[q] = l; s.alpha[q] = al;
        }
        __syncthreads();

        // Rescale accumulator, then O += P . V
        float alph[4];
#pragma unroll
        for (int i = 0; i < 4; i++) alph[i] = s.alpha[ty * 4 + i];
#pragma unroll
        for (int i = 0; i < 4; i++)
#pragma unroll
            for (int j = 0; j < 4; j++) o[i][j] *= alph[i];

#pragma unroll 16
        for (int kk = 0; kk < BKV; kk++) {
            float4 vv = *reinterpret_cast<const float4*>(&s.Vs[kk][tx * 4]);
            float vb[4] = {vv.x, vv.y, vv.z, vv.w};
            float p[4];
#pragma unroll
            for (int i = 0; i < 4; i++) p[i] = s.Ss[ty * 4 + i][kk];
#pragma unroll
            for (int i = 0; i < 4; i++)
#pragma unroll
                for (int j = 0; j < 4; j++) o[i][j] = fmaf(p[i], vb[j], o[i][j]);
        }
    }

    // Normalize and write to g_att in [B,T,DIM] layout
    const int b = bh / NHEADS;
    const int h = bh % NHEADS;
#pragma unroll
    for (int i = 0; i < 4; i++) {
        const int q = ty * 4 + i;
        const float inv = 1.f / s.rowl[q];
        float4 r = {o[i][0] * inv, o[i][1] * inv, o[i][2] * inv, o[i][3] * inv};
        float* dst = Out + ((size_t)(b * TTOK + q0 + q)) * DIMC + h * HDIM + tx * 4;
        *reinterpret_cast<float4*>(dst) = r;
    }
}

// ============================================================================
// launch
// ============================================================================
extern "C" void kernel_launch(void* const* d_in, const int* in_sizes, int n_in,
                              void* d_out, int out_size)
{
    (void)in_sizes; (void)n_in; (void)out_size;
    const float* x  = (const float*)d_in[0];
    const float* wq = (const float*)d_in[1];
    const float* wk = (const float*)d_in[2];
    const float* wv = (const float*)d_in[3];
    const float* wo = (const float*)d_in[4];
    float* out = (float*)d_out;

    float *gq, *gk, *gv, *ga;
    cudaGetSymbolAddress((void**)&gq, g_q);
    cudaGetSymbolAddress((void**)&gk, g_k);
    cudaGetSymbolAddress((void**)&gv, g_v);
    cudaGetSymbolAddress((void**)&ga, g_att);

    cudaFuncSetAttribute(attn_kernel, cudaFuncAttributeMaxDynamicSharedMemorySize,
                         (int)sizeof(AttnSmem));

    dim3 ggrid(NTOK / BM, DIMC / BN);     // (64, 8)
    gemm_nt_kernel<<<ggrid, 256>>>(x, wq, gq, 1);
    gemm_nt_kernel<<<ggrid, 256>>>(x, wk, gk, 1);
    gemm_nt_kernel<<<ggrid, 256>>>(x, wv, gv, 1);

    dim3 agrid(TTOK / BQ, BB * NHEADS);   // (32, 64)
    attn_kernel<<<agrid, 256, sizeof(AttnSmem)>>>(gq, gk, gv, ga);

    gemm_nt_kernel<<<ggrid, 256>>>(ga, wo, out, 0);
}

// round 6
// speedup vs baseline: 1.6264x; 1.6264x over previous
#include <cuda_runtime.h>
#include <cstdint>
#include <math.h>

#define DIMC    1024
#define NHEADS  16
#define HDIM    64
#define BB      4
#define TTOK    2048
#define NTOK    (BB * TTOK)      // 8192

// ---------------- scratch (device globals; no allocations allowed) ----------
__device__ float g_q[NTOK * DIMC];    // [B,H,T,Dh]
__device__ float g_k[NTOK * DIMC];
__device__ float g_v[NTOK * DIMC];
__device__ float g_att[NTOK * DIMC];  // [B,T,DIM]

// fp32 -> tf32 bit pattern, round-to-nearest
__device__ __forceinline__ uint32_t f2tf32(float f) {
    uint32_t r;
    asm("cvt.rna.tf32.f32 %0, %1;" : "=r"(r) : "f"(f));
    return r;
}

// m16n8k8 tf32 MMA (legacy HMMA pipe, valid on sm_100 base target)
__device__ __forceinline__ void mma_tf32(float* c, const uint32_t* a, const uint32_t* b) {
    asm volatile(
        "mma.sync.aligned.m16n8k8.row.col.f32.tf32.tf32.f32 "
        "{%0,%1,%2,%3}, {%4,%5,%6,%7}, {%8,%9}, {%0,%1,%2,%3};"
        : "+f"(c[0]), "+f"(c[1]), "+f"(c[2]), "+f"(c[3])
        : "r"(a[0]), "r"(a[1]), "r"(a[2]), "r"(a[3]), "r"(b[0]), "r"(b[1]));
}

// ============================================================================
// tf32 mma.sync GEMM (NT): out[m][n] = sum_c A[m][c] * W[n][c]
// BM=128, BN=128, BK=16. 256 threads = 8 warps (4 M x 2 N), warp tile 32x64.
// Tiles in smem row-major [row][k], stride 20 words (conflict-free frag LDS).
// qkv_mode=1: write [B,H,T,Dh]; qkv_mode=0: row-major [M, DIMC].
// ============================================================================
#define GBM 128
#define GBN 128
#define GBK 16
#define GSTRIDE 20
#define NKITER (DIMC / GBK)   // 64

__global__ __launch_bounds__(256, 1)
void gemm_tf32_mma(const float* __restrict__ A,
                   const float* __restrict__ w0, const float* __restrict__ w1,
                   const float* __restrict__ w2,
                   float* __restrict__ o0, float* __restrict__ o1,
                   float* __restrict__ o2,
                   int qkv_mode)
{
    __shared__ uint32_t As[2][GBM][GSTRIDE];
    __shared__ uint32_t Bs[2][GBN][GSTRIDE];

    const float* W   = (blockIdx.z == 0) ? w0 : (blockIdx.z == 1) ? w1 : w2;
    float*       out = (blockIdx.z == 0) ? o0 : (blockIdx.z == 1) ? o1 : o2;

    const int m0   = blockIdx.x * GBM;
    const int n0   = blockIdx.y * GBN;
    const int tid  = threadIdx.x;
    const int warp = tid >> 5;
    const int lane = tid & 31;
    const int tm4  = lane & 3;     // k-quad / col-quad
    const int td4  = lane >> 2;    // row group
    const int wm0  = (warp & 3) * 32;   // warp M origin (4 warps over M)
    const int wn0  = (warp >> 2) * 64;  // warp N origin (2 warps over N)

    // per-thread gmem fetch coords: 512 float4 per tile, 2 per thread
    const int r0 = tid >> 2, c40 = (tid & 3);          // rows 0..63
    const int r1 = (tid + 256) >> 2, c41 = (tid & 3);  // rows 64..127

    float c[2][8][4];
#pragma unroll
    for (int i = 0; i < 2; i++)
#pragma unroll
        for (int j = 0; j < 8; j++)
#pragma unroll
            for (int q = 0; q < 4; q++) c[i][j][q] = 0.f;

    // ---- preload tile 0 into stage 0 ----
    {
        float4 a0 = *reinterpret_cast<const float4*>(A + (size_t)(m0 + r0) * DIMC + c40 * 4);
        float4 a1 = *reinterpret_cast<const float4*>(A + (size_t)(m0 + r1) * DIMC + c41 * 4);
        float4 b0 = *reinterpret_cast<const float4*>(W + (size_t)(n0 + r0) * DIMC + c40 * 4);
        float4 b1 = *reinterpret_cast<const float4*>(W + (size_t)(n0 + r1) * DIMC + c41 * 4);
        uint4 ta0 = {f2tf32(a0.x), f2tf32(a0.y), f2tf32(a0.z), f2tf32(a0.w)};
        uint4 ta1 = {f2tf32(a1.x), f2tf32(a1.y), f2tf32(a1.z), f2tf32(a1.w)};
        uint4 tb0 = {f2tf32(b0.x), f2tf32(b0.y), f2tf32(b0.z), f2tf32(b0.w)};
        uint4 tb1 = {f2tf32(b1.x), f2tf32(b1.y), f2tf32(b1.z), f2tf32(b1.w)};
        *reinterpret_cast<uint4*>(&As[0][r0][c40 * 4]) = ta0;
        *reinterpret_cast<uint4*>(&As[0][r1][c41 * 4]) = ta1;
        *reinterpret_cast<uint4*>(&Bs[0][r0][c40 * 4]) = tb0;
        *reinterpret_cast<uint4*>(&Bs[0][r1][c41 * 4]) = tb1;
    }
    __syncthreads();

    for (int kb = 0; kb < NKITER; kb++) {
        const int cur = kb & 1;
        const int nxt = cur ^ 1;

        // prefetch next tile to registers
        float4 fa0, fa1, fb0, fb1;
        if (kb + 1 < NKITER) {
            const int k0 = (kb + 1) * GBK;
            fa0 = *reinterpret_cast<const float4*>(A + (size_t)(m0 + r0) * DIMC + k0 + c40 * 4);
            fa1 = *reinterpret_cast<const float4*>(A + (size_t)(m0 + r1) * DIMC + k0 + c41 * 4);
            fb0 = *reinterpret_cast<const float4*>(W + (size_t)(n0 + r0) * DIMC + k0 + c40 * 4);
            fb1 = *reinterpret_cast<const float4*>(W + (size_t)(n0 + r1) * DIMC + k0 + c41 * 4);
        }

        // compute 2 k8 steps from stage cur
#pragma unroll
        for (int ks = 0; ks < 2; ks++) {
            const int k8 = ks * 8;
            uint32_t afr[2][4];
#pragma unroll
            for (int mi = 0; mi < 2; mi++) {
                const int ar = wm0 + mi * 16 + td4;
                afr[mi][0] = As[cur][ar    ][k8 + tm4];
                afr[mi][1] = As[cur][ar + 8][k8 + tm4];
                afr[mi][2] = As[cur][ar    ][k8 + tm4 + 4];
                afr[mi][3] = As[cur][ar + 8][k8 + tm4 + 4];
            }
#pragma unroll
            for (int nj = 0; nj < 8; nj++) {
                const int br = wn0 + nj * 8 + td4;
                uint32_t bfr[2];
                bfr[0] = Bs[cur][br][k8 + tm4];
                bfr[1] = Bs[cur][br][k8 + tm4 + 4];
#pragma unroll
                for (int mi = 0; mi < 2; mi++)
                    mma_tf32(c[mi][nj], afr[mi], bfr);
            }
        }

        // store prefetched tile to stage nxt
        if (kb + 1 < NKITER) {
            uint4 ta0 = {f2tf32(fa0.x), f2tf32(fa0.y), f2tf32(fa0.z), f2tf32(fa0.w)};
            uint4 ta1 = {f2tf32(fa1.x), f2tf32(fa1.y), f2tf32(fa1.z), f2tf32(fa1.w)};
            uint4 tb0 = {f2tf32(fb0.x), f2tf32(fb0.y), f2tf32(fb0.z), f2tf32(fb0.w)};
            uint4 tb1 = {f2tf32(fb1.x), f2tf32(fb1.y), f2tf32(fb1.z), f2tf32(fb1.w)};
            *reinterpret_cast<uint4*>(&As[nxt][r0][c40 * 4]) = ta0;
            *reinterpret_cast<uint4*>(&As[nxt][r1][c41 * 4]) = ta1;
            *reinterpret_cast<uint4*>(&Bs[nxt][r0][c40 * 4]) = tb0;
            *reinterpret_cast<uint4*>(&Bs[nxt][r1][c41 * 4]) = tb1;
        }
        __syncthreads();
    }

    // ---------------- epilogue ----------------
    if (qkv_mode) {
        const int b  = m0 / TTOK;
        const int t0 = m0 % TTOK;
        const int h  = (n0 + wn0) / HDIM;     // warp tile spans exactly one head
        float* base = out + (size_t)(b * NHEADS + h) * TTOK * HDIM;
#pragma unroll
        for (int mi = 0; mi < 2; mi++) {
            const int t = t0 + wm0 + mi * 16 + td4;
#pragma unroll
            for (int nj = 0; nj < 8; nj++) {
                const int d = nj * 8 + 2 * tm4;
                float2 lo = {c[mi][nj][0], c[mi][nj][1]};
                float2 hi = {c[mi][nj][2], c[mi][nj][3]};
                *reinterpret_cast<float2*>(base + (size_t)t * HDIM + d)       = lo;
                *reinterpret_cast<float2*>(base + (size_t)(t + 8) * HDIM + d) = hi;
            }
        }
    } else {
#pragma unroll
        for (int mi = 0; mi < 2; mi++) {
            const int r = m0 + wm0 + mi * 16 + td4;
#pragma unroll
            for (int nj = 0; nj < 8; nj++) {
                const int cc = n0 + wn0 + nj * 8 + 2 * tm4;
                float2 lo = {c[mi][nj][0], c[mi][nj][1]};
                float2 hi = {c[mi][nj][2], c[mi][nj][3]};
                *reinterpret_cast<float2*>(out + (size_t)r * DIMC + cc)       = lo;
                *reinterpret_cast<float2*>(out + (size_t)(r + 8) * DIMC + cc) = hi;
            }
        }
    }
}

// ============================================================================
// Flash attention, fp32, causal (unchanged — proven in round 1).
// ============================================================================
#define BQ   64
#define BKV  64
#define APAD 4
#define NEG_BIG (-1e30f)

struct AttnSmem {
    float Qs[HDIM][BQ + APAD];
    float Ks[HDIM][BKV + APAD];
    float Vs[BKV][HDIM + APAD];
    float Ss[BQ][BKV + APAD];
    float rowm[BQ];
    float rowl[BQ];
    float alpha[BQ];
};

__global__ __launch_bounds__(256)
void attn_kernel(const float* __restrict__ Q, const float* __restrict__ K,
                 const float* __restrict__ V, float* __restrict__ Out)
{
    extern __shared__ __align__(16) char smem_raw[];
    AttnSmem& s = *reinterpret_cast<AttnSmem*>(smem_raw);

    const int qt  = blockIdx.x;
    const int bh  = blockIdx.y;
    const int q0  = qt * BQ;
    const int tid = threadIdx.x;
    const int ty  = tid >> 4;
    const int tx  = tid & 15;

    const float* Qp = Q + (size_t)bh * TTOK * HDIM;
    const float* Kp = K + (size_t)bh * TTOK * HDIM;
    const float* Vp = V + (size_t)bh * TTOK * HDIM;

    const float scale = 0.125f;

    for (int idx = tid; idx < BQ * HDIM; idx += 256) {
        const int q = idx >> 6;
        const int d = idx & 63;
        s.Qs[d][q] = Qp[(size_t)(q0 + q) * HDIM + d] * scale;
    }
    if (tid < BQ) { s.rowm[tid] = NEG_BIG; s.rowl[tid] = 0.f; }

    float o[4][4];
#pragma unroll
    for (int i = 0; i < 4; i++)
#pragma unroll
        for (int j = 0; j < 4; j++) o[i][j] = 0.f;

    for (int jt = 0; jt <= qt; jt++) {
        const int k0 = jt * BKV;
        __syncthreads();

        for (int idx = tid; idx < BKV * HDIM; idx += 256) {
            const int kk = idx >> 6;
            const int d  = idx & 63;
            s.Ks[d][kk] = Kp[(size_t)(k0 + kk) * HDIM + d];
            s.Vs[kk][d] = Vp[(size_t)(k0 + kk) * HDIM + d];
        }
        __syncthreads();

        float acc[4][4];
#pragma unroll
        for (int i = 0; i < 4; i++)
#pragma unroll
            for (int j = 0; j < 4; j++) acc[i][j] = 0.f;

#pragma unroll 16
        for (int d = 0; d < HDIM; d++) {
            float4 qv = *reinterpret_cast<const float4*>(&s.Qs[d][ty * 4]);
            float4 kv = *reinterpret_cast<const float4*>(&s.Ks[d][tx * 4]);
            float qa[4] = {qv.x, qv.y, qv.z, qv.w};
            float kb[4] = {kv.x, kv.y, kv.z, kv.w};
#pragma unroll
            for (int i = 0; i < 4; i++)
#pragma unroll
                for (int j = 0; j < 4; j++) acc[i][j] = fmaf(qa[i], kb[j], acc[i][j]);
        }

        const bool diag = (jt == qt);
#pragma unroll
        for (int i = 0; i < 4; i++) {
            const int qg = q0 + ty * 4 + i;
            float4 r;
            float* rp = &r.x;
#pragma unroll
            for (int j = 0; j < 4; j++) {
                float v = acc[i][j];
                if (diag && (k0 + tx * 4 + j > qg)) v = NEG_BIG;
                rp[j] = v;
            }
            *reinterpret_cast<float4*>(&s.Ss[ty * 4 + i][tx * 4]) = r;
        }
        __syncthreads();

        if (tid < BQ) {
            const int q = tid;
            const float mo = s.rowm[q];
            float mx = mo;
#pragma unroll 8
            for (int k = 0; k < BKV; k++) mx = fmaxf(mx, s.Ss[q][k]);
            const float al = __expf(mo - mx);
            float l = s.rowl[q] * al;
#pragma unroll 8
            for (int k = 0; k < BKV; k++) {
                const float p = __expf(s.Ss[q][k] - mx);
                s.Ss[q][k] = p;
                l += p;
            }
            s.rowm[q] = mx; s.rowl[q] = l; s.alpha[q] = al;
        }
        __syncthreads();

        float alph[4];
#pragma unroll
        for (int i = 0; i < 4; i++) alph[i] = s.alpha[ty * 4 + i];
#pragma unroll
        for (int i = 0; i < 4; i++)
#pragma unroll
            for (int j = 0; j < 4; j++) o[i][j] *= alph[i];

#pragma unroll 16
        for (int kk = 0; kk < BKV; kk++) {
            float4 vv = *reinterpret_cast<const float4*>(&s.Vs[kk][tx * 4]);
            float vb[4] = {vv.x, vv.y, vv.z, vv.w};
            float p[4];
#pragma unroll
            for (int i = 0; i < 4; i++) p[i] = s.Ss[ty * 4 + i][kk];
#pragma unroll
            for (int i = 0; i < 4; i++)
#pragma unroll
                for (int j = 0; j < 4; j++) o[i][j] = fmaf(p[i], vb[j], o[i][j]);
        }
    }

    const int b = bh / NHEADS;
    const int h = bh % NHEADS;
#pragma unroll
    for (int i = 0; i < 4; i++) {
        const int q = ty * 4 + i;
        const float inv = 1.f / s.rowl[q];
        float4 r = {o[i][0] * inv, o[i][1] * inv, o[i][2] * inv, o[i][3] * inv};
        float* dst = Out + ((size_t)(b * TTOK + q0 + q)) * DIMC + h * HDIM + tx * 4;
        *reinterpret_cast<float4*>(dst) = r;
    }
}

// ============================================================================
// launch
// ============================================================================
extern "C" void kernel_launch(void* const* d_in, const int* in_sizes, int n_in,
                              void* d_out, int out_size)
{
    (void)in_sizes; (void)n_in; (void)out_size;
    const float* x  = (const float*)d_in[0];
    const float* wq = (const float*)d_in[1];
    const float* wk = (const float*)d_in[2];
    const float* wv = (const float*)d_in[3];
    const float* wo = (const float*)d_in[4];
    float* out = (float*)d_out;

    float *gq, *gk, *gv, *ga;
    cudaGetSymbolAddress((void**)&gq, g_q);
    cudaGetSymbolAddress((void**)&gk, g_k);
    cudaGetSymbolAddress((void**)&gv, g_v);
    cudaGetSymbolAddress((void**)&ga, g_att);

    cudaFuncSetAttribute(attn_kernel, cudaFuncAttributeMaxDynamicSharedMemorySize,
                         (int)sizeof(AttnSmem));

    // fused QKV projections: grid.z picks weight/output
    dim3 qkv_grid(NTOK / GBM, DIMC / GBN, 3);    // (64, 8, 3)
    gemm_tf32_mma<<<qkv_grid, 256>>>(x, wq, wk, wv, gq, gk, gv, 1);

    dim3 agrid(TTOK / BQ, BB * NHEADS);          // (32, 64)
    attn_kernel<<<agrid, 256, sizeof(AttnSmem)>>>(gq, gk, gv, ga);

    // output projection
    dim3 o_grid(NTOK / GBM, DIMC / GBN, 1);      // (64, 8, 1)
    gemm_tf32_mma<<<o_grid, 256>>>(ga, wo, wo, wo, out, out, out, 0);
}